// round 7
// baseline (speedup 1.0000x reference)
#include <cuda_runtime.h>
#include <cuda_fp16.h>
#include <cstdint>

#define NB 65536

// ============================ device scratch ============================
__device__ int g_cnt[16];
__device__ int g_gidx[16][NB];
__device__ __align__(16) float g_h[(size_t)NB * 256];
__device__ __align__(16) float g_bufA[(size_t)NB * 384];
__device__ __align__(16) float g_bufB[(size_t)NB * 384];
// fp16 hi/lo weight planes, n-major [e][n][k], hi plane then lo plane per layer
__device__ __align__(16) __half g_wprep[3407872];

// layer offsets into g_wprep (half units)
static const size_t OFF_W0_0 = 0;
static const size_t OFF_W0_1 = 65536;
static const size_t OFF_W1p  = 327680;
static const size_t OFF_W1_0 = 393216;
static const size_t OFF_W1_1 = 1179648;
static const size_t OFF_W2p  = 1441792;
static const size_t OFF_W2_0 = 1507328;
static const size_t OFF_W2_1 = 2293760;
static const size_t OFF_W3p  = 2555904;
static const size_t OFF_W3_0 = 2621440;

// ============================ routing ============================
__global__ void k_zero() { if (threadIdx.x < 16) g_cnt[threadIdx.x] = 0; }

__global__ void k_route(const float* __restrict__ in) {
    int row = blockIdx.x * 256 + threadIdx.x;
    if (row >= NB) return;
    int lane = threadIdx.x & 31;
    const float* oh = in + (size_t)row * 144 + 128;
    #pragma unroll
    for (int j = 0; j < 4; j++) {
        int e = 0;
        #pragma unroll
        for (int t = 1; t < 4; t++) if (oh[j * 4 + t] > 0.5f) e = t;
        #pragma unroll
        for (int ee = 0; ee < 4; ee++) {
            unsigned m = __ballot_sync(0xffffffffu, e == ee);
            if (e == ee) {
                int leader = __ffs(m) - 1, base = 0;
                if (lane == leader) base = atomicAdd(&g_cnt[j * 4 + ee], __popc(m));
                base = __shfl_sync(m, base, leader);
                g_gidx[j * 4 + ee][base + __popc(m & ((1u << lane) - 1u))] = row;
            }
        }
    }
}

// ============================ fused weight prep ============================
struct PrepArgs { const float* W[10]; };
__constant__ int c_in[10]   = {32, 256, 32, 384, 256, 32, 384, 256, 32, 384};
__constant__ int c_out[10]  = {256, 128, 256, 256, 128, 256, 256, 128, 256, 256};
__constant__ int c_cum[10]  = {0, 32768, 163840, 196608, 589824,
                               720896, 753664, 1146880, 1277952, 1310720};
__constant__ size_t c_base[10] = {OFF_W0_0, OFF_W0_1, OFF_W1p, OFF_W1_0, OFF_W1_1,
                                  OFF_W2p, OFF_W2_0, OFF_W2_1, OFF_W3p, OFF_W3_0};
#define PREP_TOTAL 1703936

__global__ void k_prep_all(PrepArgs pa) {
    for (int id = blockIdx.x * 256 + threadIdx.x; id < PREP_TOTAL; id += gridDim.x * 256) {
        int s = 9;
        #pragma unroll
        for (int i = 1; i < 10; i++) if (id < c_cum[i]) { s = i - 1; break; }
        int IN = c_in[s], OUT = c_out[s];
        int local = id - c_cum[s];
        int e = local / (OUT * IN);
        int rem = local % (OUT * IN);
        int n = rem / IN, k = rem % IN;
        float v = pa.W[s][((size_t)e * IN + k) * OUT + n];
        __half h = __float2half_rn(v);
        __half l = __float2half_rn(v - __half2float(h));
        size_t o = (size_t)(e * OUT + n) * IN + k;
        g_wprep[c_base[s] + o] = h;
        g_wprep[c_base[s] + (size_t)4 * OUT * IN + o] = l;
    }
}

// ============================ mma / ldmatrix helpers ============================
#define MMA16816(c, a, b) \
    asm volatile("mma.sync.aligned.m16n8k16.row.col.f32.f16.f16.f32 " \
        "{%0,%1,%2,%3}, {%4,%5,%6,%7}, {%8,%9}, {%0,%1,%2,%3};" \
        : "+f"((c)[0]), "+f"((c)[1]), "+f"((c)[2]), "+f"((c)[3]) \
        : "r"((a)[0]), "r"((a)[1]), "r"((a)[2]), "r"((a)[3]), \
          "r"((b)[0]), "r"((b)[1]))

#define LDSM_X4(r0, r1, r2, r3, addr) \
    asm volatile("ldmatrix.sync.aligned.m8n8.x4.shared.b16 {%0,%1,%2,%3}, [%4];" \
        : "=r"(r0), "=r"(r1), "=r"(r2), "=r"(r3) : "r"(addr))

__device__ __forceinline__ uint32_t smem_u32(const void* p) {
    return (uint32_t)__cvta_generic_to_shared(p);
}

// ============================ tensor GEMM ============================
// Block: 128 gathered rows x 128 cols (blockIdx.y = col block).
// Deduped smem layout per buffer: A=[Ah(32)|Al(32)] B=[Bh(32)|Bl(32)], stride 72.
// 3-pass fp32-split realized by revisiting LDSM offsets (6 k-steps per 32-k chunk).
// Double-buffered: one __syncthreads per chunk; STS of next chunk overlaps MMAs.
template <int IN, int OUT>
__global__ __launch_bounds__(256) void k_tgemm(
        int node, int asel, int acol, const float* __restrict__ fin,
        size_t woff, const float* __restrict__ Ball,
        int csel, int ldc, int ccol) {
    constexpr int SA = 72;               // halfs per smem row (144 B, conflict-free)
    constexpr int AH = 128 * SA;         // halfs per A (or B) tile = 9216
    constexpr int PAIRB = 2 * AH * 2;    // bytes per buffer (A+B) = 36864
    constexpr int NCH = IN / 32;

    extern __shared__ __half dyn[];      // [buf0: A|B][buf1: A|B]
    __shared__ int s_ridx[128];
    __shared__ float s_bias[128];

    const int tid = threadIdx.x;
    const int cb = blockIdx.y;

    // map blockIdx.x -> (expert, tile)
    int e = -1, tile = 0, nrows = 0, acc0 = 0;
    #pragma unroll
    for (int ee = 0; ee < 4; ee++) {
        int ne = g_cnt[node * 4 + ee];
        int nt = (ne + 127) >> 7;
        if (e < 0 && (int)blockIdx.x < acc0 + nt) { e = ee; tile = (int)blockIdx.x - acc0; nrows = ne; }
        acc0 += nt;
    }
    if (e < 0) return;

    if (tid < 128) {
        int r = tile * 128 + tid;
        s_ridx[tid] = (r < nrows) ? g_gidx[node * 4 + e][r] : -1;
        s_bias[tid] = Ball[(size_t)e * OUT + cb * 128 + tid];
    }
    __syncthreads();

    const float* Aptr; int lda;
    if (asel == 0)      { Aptr = fin;    lda = 144; }
    else if (asel == 1) { Aptr = g_h;    lda = 256; }
    else if (asel == 2) { Aptr = g_bufA; lda = 384; }
    else                { Aptr = g_bufB; lda = 384; }
    float* C = (csel == 1) ? g_h : (csel == 2 ? g_bufA : g_bufB);

    const __half* wh = g_wprep + woff;
    const __half* wl = wh + (size_t)4 * OUT * IN;

    // staging assignment: thread -> row ar (0..127), half-chunk ak0 (0 or 16)
    const int ar = tid >> 1, ak0 = (tid & 1) * 16;
    const int ari = s_ridx[ar];
    const float* abase = Aptr + (size_t)(ari < 0 ? 0 : ari) * lda + acol + ak0;
    const __half* bhb = wh + ((size_t)(e * OUT + cb * 128 + ar) * IN + ak0);
    const __half* blb = wl + ((size_t)(e * OUT + cb * 128 + ar) * IN + ak0);

    float4 fA[4];
    uint4 bhv[2], blv[2];

    auto ldA = [&](int kk) {
        if (ari >= 0) {
            const float4* p = (const float4*)(abase + kk);
            fA[0] = p[0]; fA[1] = p[1]; fA[2] = p[2]; fA[3] = p[3];
        } else {
            fA[0] = fA[1] = fA[2] = fA[3] = make_float4(0.f, 0.f, 0.f, 0.f);
        }
    };
    auto ldB = [&](int kk) {
        const uint4* ph = (const uint4*)(bhb + kk);
        const uint4* pl = (const uint4*)(blb + kk);
        bhv[0] = ph[0]; bhv[1] = ph[1]; blv[0] = pl[0]; blv[1] = pl[1];
    };
    auto stA = [&](int buf) {
        float v[16] = { fA[0].x, fA[0].y, fA[0].z, fA[0].w,
                        fA[1].x, fA[1].y, fA[1].z, fA[1].w,
                        fA[2].x, fA[2].y, fA[2].z, fA[2].w,
                        fA[3].x, fA[3].y, fA[3].z, fA[3].w };
        unsigned H[8], L[8];
        #pragma unroll
        for (int p = 0; p < 8; p++) {
            float v0 = v[2 * p], v1 = v[2 * p + 1];
            __half h0 = __float2half_rn(v0), h1 = __float2half_rn(v1);
            __half l0 = __float2half_rn(v0 - __half2float(h0));
            __half l1 = __float2half_rn(v1 - __half2float(h1));
            H[p] = ((unsigned)__half_as_ushort(h1) << 16) | __half_as_ushort(h0);
            L[p] = ((unsigned)__half_as_ushort(l1) << 16) | __half_as_ushort(l0);
        }
        __half* r = dyn + buf * 2 * AH + ar * SA;
        *(uint4*)(r + ak0)          = make_uint4(H[0], H[1], H[2], H[3]);  // Ah
        *(uint4*)(r + ak0 + 8)      = make_uint4(H[4], H[5], H[6], H[7]);
        *(uint4*)(r + 32 + ak0)     = make_uint4(L[0], L[1], L[2], L[3]);  // Al
        *(uint4*)(r + 32 + ak0 + 8) = make_uint4(L[4], L[5], L[6], L[7]);
    };
    auto stB = [&](int buf) {
        __half* r = dyn + buf * 2 * AH + AH + ar * SA;
        *(uint4*)(r + ak0)          = bhv[0];  // Bh
        *(uint4*)(r + ak0 + 8)      = bhv[1];
        *(uint4*)(r + 32 + ak0)     = blv[0];  // Bl
        *(uint4*)(r + 32 + ak0 + 8) = blv[1];
    };

    // warp layout: 4 (m) x 2 (n); warp tile 32 rows x 64 cols
    const int w = tid >> 5, lane = tid & 31;
    const int m0 = (w >> 1) * 32, n0 = (w & 1) * 64;
    const int g = lane >> 2, t4 = lane & 3;
    const int q = lane >> 3;                 // ldmatrix quadrant 0..3

    const uint32_t base32 = smem_u32(dyn);
    uint32_t aRel[2], bRel[4];
    #pragma unroll
    for (int ms = 0; ms < 2; ms++)
        aRel[ms] = (uint32_t)(((m0 + ms * 16 + (lane & 7) + (q & 1) * 8) * SA
                               + (q >> 1) * 8) * 2);
    #pragma unroll
    for (int j = 0; j < 4; j++)
        bRel[j] = (uint32_t)((AH + (n0 + (2 * j + (q >> 1)) * 8 + (lane & 7)) * SA
                              + (q & 1) * 8) * 2);

    // split passes via offset reuse (bytes): A {Ah,Ah,Al,Al,Ah,Ah}, B {Bh,Bh,Bh,Bh,Bl,Bl}
    constexpr int aOff[6] = {0, 32, 64, 96, 0, 32};
    constexpr int bOff[6] = {0, 32, 0, 32, 64, 96};

    float acc[2][8][4];
    #pragma unroll
    for (int i = 0; i < 2; i++)
        #pragma unroll
        for (int j = 0; j < 8; j++)
            #pragma unroll
            for (int c = 0; c < 4; c++) acc[i][j][c] = 0.f;

    ldA(0); ldB(0);
    stA(0); stB(0);
    __syncthreads();
    for (int ch = 0; ch < NCH; ch++) {
        if (ch + 1 < NCH) { ldA((ch + 1) * 32); ldB((ch + 1) * 32); }
        const uint32_t bufb = base32 + (uint32_t)(ch & 1) * PAIRB;
        #pragma unroll
        for (int ks = 0; ks < 6; ks++) {
            unsigned a[2][4], b[8][2];
            #pragma unroll
            for (int ms = 0; ms < 2; ms++)
                LDSM_X4(a[ms][0], a[ms][1], a[ms][2], a[ms][3],
                        bufb + aRel[ms] + aOff[ks]);
            #pragma unroll
            for (int j = 0; j < 4; j++)
                LDSM_X4(b[2 * j][0], b[2 * j][1], b[2 * j + 1][0], b[2 * j + 1][1],
                        bufb + bRel[j] + bOff[ks]);
            #pragma unroll
            for (int ms = 0; ms < 2; ms++)
                #pragma unroll
                for (int ns = 0; ns < 8; ns++)
                    MMA16816(acc[ms][ns], a[ms], b[ns]);
        }
        if (ch + 1 < NCH) { stA((ch + 1) & 1); stB((ch + 1) & 1); }
        __syncthreads();
    }

    // epilogue: bias + relu, scatter fp32
    #pragma unroll
    for (int ms = 0; ms < 2; ms++) {
        int r0 = m0 + ms * 16 + g;
        int ri = s_ridx[r0], rj = s_ridx[r0 + 8];
        float* c0p = C + (size_t)(ri < 0 ? 0 : ri) * ldc + ccol + cb * 128;
        float* c1p = C + (size_t)(rj < 0 ? 0 : rj) * ldc + ccol + cb * 128;
        #pragma unroll
        for (int ns = 0; ns < 8; ns++) {
            int cc = n0 + ns * 8 + 2 * t4;
            float b0 = s_bias[cc], b1 = s_bias[cc + 1];
            if (ri >= 0) {
                float2 v = make_float2(fmaxf(acc[ms][ns][0] + b0, 0.f),
                                       fmaxf(acc[ms][ns][1] + b1, 0.f));
                *(float2*)(c0p + cc) = v;
            }
            if (rj >= 0) {
                float2 v = make_float2(fmaxf(acc[ms][ns][2] + b0, 0.f),
                                       fmaxf(acc[ms][ns][3] + b1, 0.f));
                *(float2*)(c1p + cc) = v;
            }
        }
    }
}

// ============================ final 256->8 head (no relu) ============================
__global__ __launch_bounds__(256) void k_final(
        const float* __restrict__ in, const float* __restrict__ W,
        const float* __restrict__ Bb, float* __restrict__ out) {
    int gw = (blockIdx.x * 256 + threadIdx.x) >> 5;
    int lane = threadIdx.x & 31;
    if (gw >= NB) return;
    const float* oh = in + (size_t)gw * 144 + 140;
    int e = 0;
    #pragma unroll
    for (int t = 1; t < 4; t++) if (oh[t] > 0.5f) e = t;
    const float* h = g_h + (size_t)gw * 256;
    const float* w = W + (size_t)e * 2048;
    float acc[8] = {0, 0, 0, 0, 0, 0, 0, 0};
    #pragma unroll
    for (int kk = 0; kk < 256; kk += 32) {
        int k = kk + lane;
        float hv = h[k];
        float4 wa = *(const float4*)(w + k * 8);
        float4 wb = *(const float4*)(w + k * 8 + 4);
        acc[0] += hv * wa.x; acc[1] += hv * wa.y; acc[2] += hv * wa.z; acc[3] += hv * wa.w;
        acc[4] += hv * wb.x; acc[5] += hv * wb.y; acc[6] += hv * wb.z; acc[7] += hv * wb.w;
    }
    #pragma unroll
    for (int o = 16; o > 0; o >>= 1)
        #pragma unroll
        for (int c = 0; c < 8; c++) acc[c] += __shfl_xor_sync(0xffffffffu, acc[c], o);
    if (lane < 8) {
        float v = acc[0];
        switch (lane) {
            case 1: v = acc[1]; break; case 2: v = acc[2]; break;
            case 3: v = acc[3]; break; case 4: v = acc[4]; break;
            case 5: v = acc[5]; break; case 6: v = acc[6]; break;
            case 7: v = acc[7]; break; default: break;
        }
        out[(size_t)gw * 8 + lane] = v + Bb[e * 8 + lane];
    }
}

// ============================ launch ============================
extern "C" void kernel_launch(void* const* d_in, const int* in_sizes, int n_in,
                              void* d_out, int out_size) {
    const float* in = (const float*)d_in[0];
    float* out = (float*)d_out;
    auto P = [&](int i) { return (const float*)d_in[i]; };

    const int DSM = 2 * 2 * 128 * 72 * 2;   // 73728 B: double-buffered A+B
    cudaFuncSetAttribute((const void*)k_tgemm<32, 256>,
                         cudaFuncAttributeMaxDynamicSharedMemorySize, DSM);
    cudaFuncSetAttribute((const void*)k_tgemm<256, 128>,
                         cudaFuncAttributeMaxDynamicSharedMemorySize, DSM);
    cudaFuncSetAttribute((const void*)k_tgemm<384, 256>,
                         cudaFuncAttributeMaxDynamicSharedMemorySize, DSM);

    PrepArgs pa;
    pa.W[0] = P(1);  pa.W[1] = P(3);  pa.W[2] = P(5);  pa.W[3] = P(7);  pa.W[4] = P(9);
    pa.W[5] = P(11); pa.W[6] = P(13); pa.W[7] = P(15); pa.W[8] = P(17); pa.W[9] = P(19);
    k_prep_all<<<1024, 256>>>(pa);

    k_zero<<<1, 16>>>();
    k_route<<<NB / 256, 256>>>(in);

    dim3 g2(516, 2), g1(516, 1);
    // node 0
    k_tgemm<32, 256><<<g2, 256, DSM>>>(0, 0, 0,  in, OFF_W0_0, P(2),  1, 256, 0);
    k_tgemm<256, 128><<<g1, 256, DSM>>>(0, 1, 0,  in, OFF_W0_1, P(4),  2, 384, 0);
    // node 1
    k_tgemm<32, 256><<<g2, 256, DSM>>>(1, 0, 32, in, OFF_W1p,  P(6),  2, 384, 128);
    k_tgemm<384, 256><<<g2, 256, DSM>>>(1, 2, 0,  in, OFF_W1_0, P(8),  1, 256, 0);
    k_tgemm<256, 128><<<g1, 256, DSM>>>(1, 1, 0,  in, OFF_W1_1, P(10), 3, 384, 0);
    // node 2
    k_tgemm<32, 256><<<g2, 256, DSM>>>(2, 0, 64, in, OFF_W2p,  P(12), 3, 384, 128);
    k_tgemm<384, 256><<<g2, 256, DSM>>>(2, 3, 0,  in, OFF_W2_0, P(14), 1, 256, 0);
    k_tgemm<256, 128><<<g1, 256, DSM>>>(2, 1, 0,  in, OFF_W2_1, P(16), 2, 384, 0);
    // node 3
    k_tgemm<32, 256><<<g2, 256, DSM>>>(3, 0, 96, in, OFF_W3p,  P(18), 2, 384, 128);
    k_tgemm<384, 256><<<g2, 256, DSM>>>(3, 2, 0,  in, OFF_W3_0, P(20), 1, 256, 0);
    // final head
    k_final<<<NB / 8, 256>>>(in, P(21), P(22), out);
}